// round 1
// baseline (speedup 1.0000x reference)
#include <cuda_runtime.h>
#include <cuda_bf16.h>
#include <math.h>

#define B 8
#define A 120000
#define C 80
#define NPAD 1024
#define TOPN 1000
#define MAXDET 100
#define CANDMAX 4096

// ---------------- scratch (device globals; no allocation allowed) ----------------
__device__ float              g_scores[B * A];
__device__ int                g_classes[B * A];
__device__ int                g_hist1[B * 1024];
__device__ int                g_hist2[B * 4096];
__device__ int                g_b1[B];
__device__ int                g_above[B];
__device__ unsigned           g_P[B];
__device__ int                g_ccnt[B];
__device__ unsigned long long g_cand[B * CANDMAX];
__device__ float              g_tscore[B * NPAD];
__device__ int                g_tcls[B * NPAD];
__device__ float4             g_tbox[B * NPAD];
__device__ float              g_tarea[B * NPAD];
__device__ unsigned           g_mask[B * NPAD * 32];

// ---------------- K0: zero histograms / counters (graph replays!) ----------------
__global__ void k_zero() {
    int i = blockIdx.x * blockDim.x + threadIdx.x;
    if (i < B * 1024) g_hist1[i] = 0;
    if (i < B * 4096) g_hist2[i] = 0;
    if (i < B)        g_ccnt[i]  = 0;
}

// ---------------- K1: max/argmax over 80 classes + pass-1 histogram ----------------
__global__ void __launch_bounds__(256) k_scores(const float* __restrict__ cls) {
    int img = blockIdx.y;
    int a   = blockIdx.x * blockDim.x + threadIdx.x;
    __shared__ int h[1024];
    for (int i = threadIdx.x; i < 1024; i += blockDim.x) h[i] = 0;
    __syncthreads();
    if (a < A) {
        const float4* p = (const float4*)(cls + ((size_t)img * A + a) * C);
        float best = -1e30f; int bi = 0;
#pragma unroll
        for (int i = 0; i < C / 4; i++) {
            float4 v = p[i];
            if (v.x > best) { best = v.x; bi = 4 * i + 0; }
            if (v.y > best) { best = v.y; bi = 4 * i + 1; }
            if (v.z > best) { best = v.z; bi = 4 * i + 2; }
            if (v.w > best) { best = v.w; bi = 4 * i + 3; }
        }
        g_scores[img * A + a]  = best;
        g_classes[img * A + a] = bi;
        unsigned b = __float_as_uint(best) >> 20;   // positive floats: bits are order-iso
        if (b > 1023u) b = 1023u;
        atomicAdd(&h[b], 1);
    }
    __syncthreads();
    for (int i = threadIdx.x; i < 1024; i += blockDim.x)
        if (h[i]) atomicAdd(&g_hist1[img * 1024 + i], h[i]);
}

// ---------------- K2: scan pass-1 hist (top-down) ----------------
__global__ void __launch_bounds__(1024) k_scan1() {
    int img = blockIdx.x, tid = threadIdx.x;
    __shared__ int ps[1024];
    int v = g_hist1[img * 1024 + (1023 - tid)];
    ps[tid] = v;
    __syncthreads();
    for (int off = 1; off < 1024; off <<= 1) {
        int t = (tid >= off) ? ps[tid - off] : 0;
        __syncthreads();
        ps[tid] += t;
        __syncthreads();
    }
    int cum = ps[tid];  // count of elements in bins >= (1023-tid)
    if (cum >= TOPN && cum - v < TOPN) {
        g_b1[img]    = 1023 - tid;
        g_above[img] = cum - v;
    }
}

// ---------------- K3: pass-2 histogram within chosen bin ----------------
__global__ void __launch_bounds__(256) k_hist2() {
    int img = blockIdx.y;
    __shared__ int h[4096];
    for (int i = threadIdx.x; i < 4096; i += blockDim.x) h[i] = 0;
    __syncthreads();
    int i  = blockIdx.x * blockDim.x + threadIdx.x;
    int b1 = g_b1[img];
    if (i < A) {
        unsigned bits = __float_as_uint(g_scores[img * A + i]);
        if ((int)(bits >> 20) == b1) atomicAdd(&h[(bits >> 8) & 0xFFFu], 1);
    }
    __syncthreads();
    for (int i2 = threadIdx.x; i2 < 4096; i2 += blockDim.x)
        if (h[i2]) atomicAdd(&g_hist2[img * 4096 + i2], h[i2]);
}

// ---------------- K4: scan pass-2 hist -> exact prefix threshold P ----------------
__global__ void __launch_bounds__(1024) k_scan2() {
    int img = blockIdx.x, tid = threadIdx.x;
    __shared__ int ps[1024];
    int v[4]; int s = 0;
#pragma unroll
    for (int j = 0; j < 4; j++) {
        int r = tid * 4 + j;
        v[j] = g_hist2[img * 4096 + (4095 - r)];
        s += v[j];
    }
    ps[tid] = s;
    __syncthreads();
    for (int off = 1; off < 1024; off <<= 1) {
        int t = (tid >= off) ? ps[tid - off] : 0;
        __syncthreads();
        ps[tid] += t;
        __syncthreads();
    }
    int excl = ((tid > 0) ? ps[tid - 1] : 0) + g_above[img];
    int b1   = g_b1[img];
    int cum  = excl;
#pragma unroll
    for (int j = 0; j < 4; j++) {
        cum += v[j];
        if (cum >= TOPN && cum - v[j] < TOPN) {
            int bin  = 4095 - (tid * 4 + j);
            g_P[img] = ((unsigned)b1 << 12) | (unsigned)bin;
        }
    }
}

// ---------------- K5: compact candidates (bits>>8 >= P) ----------------
__global__ void __launch_bounds__(256) k_compact() {
    int img = blockIdx.y;
    int i   = blockIdx.x * blockDim.x + threadIdx.x;
    if (i < A) {
        unsigned bits = __float_as_uint(g_scores[img * A + i]);
        if ((bits >> 8) >= g_P[img]) {
            int pos = atomicAdd(&g_ccnt[img], 1);
            if (pos < CANDMAX)
                g_cand[img * CANDMAX + pos] =
                    ((unsigned long long)bits << 32) | (unsigned)(~(unsigned)i);
        }
    }
}

// ---------------- K6: per-image bitonic sort + gather + decode ----------------
__global__ void __launch_bounds__(1024) k_sortdec(const float* __restrict__ reg,
                                                  const float* __restrict__ anc) {
    int img = blockIdx.x, tid = threadIdx.x;
    __shared__ unsigned long long keys[CANDMAX];
    int cnt = g_ccnt[img];
    if (cnt > CANDMAX) cnt = CANDMAX;
    for (int i = tid; i < CANDMAX; i += 1024)
        keys[i] = (i < cnt) ? g_cand[img * CANDMAX + i] : 0ULL;
    __syncthreads();
    for (int k = 2; k <= CANDMAX; k <<= 1) {
        for (int j = k >> 1; j > 0; j >>= 1) {
            for (int i = tid; i < CANDMAX; i += 1024) {
                int ixj = i ^ j;
                if (ixj > i) {
                    unsigned long long va = keys[i], vb = keys[ixj];
                    bool up = ((i & k) == 0);
                    if ((va > vb) == up) { keys[i] = vb; keys[ixj] = va; }
                }
            }
            __syncthreads();
        }
    }
    if (tid < TOPN) {
        unsigned long long kk = keys[CANDMAX - 1 - tid];  // rank tid (desc, stable)
        unsigned bits = (unsigned)(kk >> 32);
        int idx = (int)(~(unsigned)(kk & 0xffffffffu));
        float score = __uint_as_float(bits);
        g_tscore[img * NPAD + tid] = score;
        size_t gi = (size_t)img * A + idx;
        g_tcls[img * NPAD + tid] = g_classes[gi];
        float4 r4 = ((const float4*)reg)[gi];
        float4 a4 = ((const float4*)anc)[gi];
        // decode — explicit rn ops to mirror XLA (no FMA contraction)
        float aw  = __fsub_rn(a4.z, a4.x);
        float ah  = __fsub_rn(a4.w, a4.y);
        float acx = __fadd_rn(a4.x, __fmul_rn(0.5f, aw));
        float acy = __fadd_rn(a4.y, __fmul_rn(0.5f, ah));
        float r0 = __fmul_rn(r4.x, 0.1f);
        float r1 = __fmul_rn(r4.y, 0.1f);
        float r2 = __fmul_rn(r4.z, 0.2f);
        float r3 = __fmul_rn(r4.w, 0.2f);
        float pw  = __fmul_rn(expf(r2), aw);
        float ph  = __fmul_rn(expf(r3), ah);
        float pcx = __fadd_rn(__fmul_rn(r0, aw), acx);
        float pcy = __fadd_rn(__fmul_rn(r1, ah), acy);
        float x1 = truncf(__fsub_rn(pcx, __fmul_rn(0.5f, pw)));
        float y1 = truncf(__fsub_rn(pcy, __fmul_rn(0.5f, ph)));
        float x2 = truncf(__fadd_rn(pcx, __fmul_rn(0.5f, pw)));
        float y2 = truncf(__fadd_rn(pcy, __fmul_rn(0.5f, ph)));
        x1 = fmaxf(x1, 0.0f);
        y1 = fmaxf(y1, 0.0f);
        x2 = fminf(x2, 639.0f);
        y2 = fminf(y2, 639.0f);
        g_tbox[img * NPAD + tid]  = make_float4(x1, y1, x2, y2);
        g_tarea[img * NPAD + tid] = __fmul_rn(__fsub_rn(x2, x1), __fsub_rn(y2, y1));
    }
}

// ---------------- K7: suppression bitmask (iou>0.5 & j>i), exact integer test ----------------
__global__ void __launch_bounds__(256) k_mask() {
    int img = blockIdx.y;
    __shared__ float4 sb[TOPN];
    __shared__ float  sa[TOPN];
    int tid = threadIdx.x;
    for (int i = tid; i < TOPN; i += 256) {
        sb[i] = g_tbox[img * NPAD + i];
        sa[i] = g_tarea[img * NPAD + i];
    }
    __syncthreads();
    int warp = tid >> 5, lane = tid & 31;
    for (int r = warp; r < 64; r += 8) {
        int i = blockIdx.x * 64 + r;   // i in [0,1024)
        float4 bi = make_float4(0.f, 0.f, 0.f, 0.f);
        float  ai = 0.f;
        if (i < TOPN) { bi = sb[i]; ai = sa[i]; }
        for (int it = 0; it < 32; it++) {
            int j = it * 32 + lane;
            bool supp = false;
            if (i < TOPN && j < TOPN && j > i) {
                float4 bj = sb[j];
                float ltx = fmaxf(bi.x, bj.x), lty = fmaxf(bi.y, bj.y);
                float rbx = fminf(bi.z, bj.z), rby = fminf(bi.w, bj.w);
                float w = fmaxf(__fsub_rn(rbx, ltx), 0.0f);
                float h = fmaxf(__fsub_rn(rby, lty), 0.0f);
                float inter = __fmul_rn(w, h);
                float s   = __fadd_rn(ai, sa[j]);
                float uni = __fsub_rn(s, inter);
                // exact equivalent of fl(inter/uni) > 0.5 on integer-valued fp32
                supp = (uni > 0.0f) ? (__fmul_rn(3.0f, inter) > s)
                                    : (uni == 0.0f && inter > 0.0f);
            }
            unsigned word = __ballot_sync(0xffffffffu, supp);
            if (lane == 0) g_mask[(img * NPAD + i) * 32 + it] = word;
        }
    }
}

// ---------------- K8: serial greedy NMS (chunked warp scan) + outputs ----------------
__global__ void __launch_bounds__(256) k_nms(float* __restrict__ out) {
    int img = blockIdx.x;
    extern __shared__ unsigned sm[];
    unsigned* s_mask = sm;                           // 32768 words
    float*    s_sc   = (float*)(sm + 32768);         // 1024
    unsigned* s_val  = (unsigned*)(s_sc + 1024);     // 32
    unsigned* s_keep = s_val + 32;                   // 32
    int*      s_kept = (int*)(s_keep + 32);          // 100
    int*      s_nk   = s_kept + MAXDET;              // 1

    int tid = threadIdx.x;
    for (int i = tid; i < 32768; i += 256) s_mask[i] = g_mask[img * 32768 + i];
    for (int i = tid; i < 1024; i += 256)
        s_sc[i] = (i < TOPN) ? g_tscore[img * NPAD + i] : -1.0f;
    __syncthreads();
    int warp = tid >> 5, lane = tid & 31;
    for (int c = warp; c < 32; c += 8) {
        unsigned vm = __ballot_sync(0xffffffffu, s_sc[c * 32 + lane] > 0.05f);
        if (lane == 0) s_val[c] = vm;
    }
    __syncthreads();

    if (warp == 0) {
        unsigned rem = 0;  // lane owns removed-bitmap word `lane`
        for (int c = 0; c < 32; c++) {
            unsigned remc = __shfl_sync(0xffffffffu, rem, c);
            unsigned vm = s_val[c];
            unsigned mcol[32];
#pragma unroll
            for (int b = 0; b < 32; b++) mcol[b] = s_mask[(c * 32 + b) * 32 + c];
            unsigned keep = 0;
#pragma unroll
            for (int b = 0; b < 32; b++) {
                if (((vm >> b) & 1u) && !((remc >> b) & 1u)) {
                    keep |= (1u << b);
                    remc |= mcol[b];
                }
            }
            unsigned mrow[32];
#pragma unroll
            for (int b = 0; b < 32; b++) mrow[b] = s_mask[(c * 32 + b) * 32 + lane];
#pragma unroll
            for (int b = 0; b < 32; b++)
                if ((keep >> b) & 1u) rem |= mrow[b];
            if (lane == 0) s_keep[c] = keep;
        }
        __syncwarp();
        // kept list in index order (== score-descending order)
        unsigned kb = s_keep[lane];
        int pc = __popc(kb);
        int x = pc;
        for (int off = 1; off < 32; off <<= 1) {
            int y = __shfl_up_sync(0xffffffffu, x, off);
            if (lane >= off) x += y;
        }
        if (lane == 31) *s_nk = x;
        int off = x - pc;
        while (kb) {
            int b = __ffs(kb) - 1;
            kb &= kb - 1;
            if (off < MAXDET) s_kept[off] = lane * 32 + b;
            off++;
        }
    }
    __syncthreads();

    if (tid < MAXDET) {
        int nk = *s_nk;
        float so = -1.0f, co = -1.0f;
        float4 bo = make_float4(-1.0f, -1.0f, -1.0f, -1.0f);
        if (tid < nk) {
            int i = s_kept[tid];
            so = s_sc[i];
            co = (float)g_tcls[img * NPAD + i];
            bo = g_tbox[img * NPAD + i];
        }
        out[img * MAXDET + tid]                = so;
        out[B * MAXDET + img * MAXDET + tid]   = co;
        float* ob = out + 2 * B * MAXDET + (img * MAXDET + tid) * 4;
        ob[0] = bo.x; ob[1] = bo.y; ob[2] = bo.z; ob[3] = bo.w;
    }
}

// ---------------- launch ----------------
extern "C" void kernel_launch(void* const* d_in, const int* in_sizes, int n_in,
                              void* d_out, int out_size) {
    const float* cls = (const float*)d_in[0];
    const float* reg = (const float*)d_in[1];
    const float* anc = (const float*)d_in[2];
    float* out = (float*)d_out;
    (void)in_sizes; (void)n_in; (void)out_size;

    const int NMS_SMEM = 32768 * 4 + 1024 * 4 + 32 * 4 + 32 * 4 + MAXDET * 4 + 4;
    cudaFuncSetAttribute(k_nms, cudaFuncAttributeMaxDynamicSharedMemorySize, NMS_SMEM);

    const int GRID_A = (A + 255) / 256;  // 469
    k_zero<<<32, 1024>>>();
    k_scores<<<dim3(GRID_A, B), 256>>>(cls);
    k_scan1<<<B, 1024>>>();
    k_hist2<<<dim3(GRID_A, B), 256>>>();
    k_scan2<<<B, 1024>>>();
    k_compact<<<dim3(GRID_A, B), 256>>>();
    k_sortdec<<<B, 1024>>>(reg, anc);
    k_mask<<<dim3(16, B), 256>>>();
    k_nms<<<B, 256, NMS_SMEM>>>(out);
}